// round 11
// baseline (speedup 1.0000x reference)
#include <cuda_runtime.h>
#include <math.h>
#include <stdint.h>

#define BB 2
#define NN 8192
#define KK 32
#define CC 128
#define HH 128
#define ALPHA 0.3f
#define EPS 1e-6f

#define RT 64                  // rows per block tile
#define AST 132                // As/Vs stride in 4B words (132%32==4 -> cf frags)
#define BSTW 132               // Bs stride in 4B words
#define AS_WORDS (RT * AST)    // 8448
#define BS_WORDS (128 * BSTW)  // 16896
#define SMEM_BYTES ((AS_WORDS + BS_WORDS) * 4)   // 101376 B -> 2 blocks/SM
#define NT 512                 // threads per GEMM block

__device__ float g_H[(size_t)BB * NN * HH];    // leaky(emb @ Qw + Qb), 8 MB
__device__ float g_wsh[(size_t)BB * NN * HH];  // weighted-sum hidden,  8 MB

__device__ __forceinline__ uint32_t to_tf32(float f) {
    uint32_t r;
    asm("cvt.rna.tf32.f32 %0, %1;" : "=r"(r) : "f"(f));
    return r;
}
__device__ __forceinline__ void mma_tf32(float c[4], uint32_t a0, uint32_t a1,
                                         uint32_t a2, uint32_t a3,
                                         uint32_t b0, uint32_t b1) {
    asm("mma.sync.aligned.m16n8k8.row.col.f32.tf32.tf32.f32 "
        "{%0,%1,%2,%3}, {%4,%5,%6,%7}, {%8,%9}, {%0,%1,%2,%3};"
        : "+f"(c[0]), "+f"(c[1]), "+f"(c[2]), "+f"(c[3])
        : "r"(a0), "r"(a1), "r"(a2), "r"(a3), "r"(b0), "r"(b1));
}
__device__ __forceinline__ float leaky(float v) {
    return (v >= 0.f) ? v : ALPHA * v;
}

// ---- stage A: 64 rows x 128 cols fp32 -> tf32 bits, stride AST ------------
__device__ __forceinline__ void stage_A(uint32_t* __restrict__ As,
                                        const float* __restrict__ src, int t) {
    const float4* s4 = (const float4*)src;
#pragma unroll
    for (int i = 0; i < (RT * CC / 4) / NT; i++) {   // 4 iters
        int id = t + i * NT;
        int row = id >> 5;
        int c = (id & 31) << 2;
        float4 v = s4[id];
        uint4 u = make_uint4(to_tf32(v.x), to_tf32(v.y), to_tf32(v.z), to_tf32(v.w));
        *(uint4*)&As[row * AST + c] = u;
    }
}
// ---- stage B: 128 x 128 weights fp32 -> tf32 bits, stride BSTW ------------
__device__ __forceinline__ void stage_B(uint32_t* __restrict__ Bs,
                                        const float* __restrict__ W, int t) {
    const float4* s4 = (const float4*)W;
#pragma unroll
    for (int i = 0; i < (128 * 128 / 4) / NT; i++) {  // 8 iters
        int id = t + i * NT;
        int row = id >> 5;
        int c = (id & 31) << 2;
        float4 v = s4[id];
        uint4 u = make_uint4(to_tf32(v.x), to_tf32(v.y), to_tf32(v.z), to_tf32(v.w));
        *(uint4*)&Bs[row * BSTW + c] = u;
    }
}

// ---- tensor-core mainloop over K=128 --------------------------------------
// 16 warps: wn = warp&7 -> cols n0=wn*16 (2 n-tiles); wm = warp>>3 ->
// rows m0=wm*32 (2 m-tiles of 16). c[mt][nt][4] accumulators per thread.
__device__ __forceinline__ void gemm_tc_128(const uint32_t* __restrict__ As,
                                            const uint32_t* __restrict__ Bs,
                                            int lane, int m0, int n0,
                                            float c[2][2][4]) {
    const uint32_t* Ab = As + (m0 + (lane >> 2)) * AST + (lane & 3);
    const uint32_t* Bb = Bs + (lane & 3) * BSTW + n0 + (lane >> 2);
#pragma unroll 4
    for (int ks = 0; ks < 16; ks++) {
        const int kb = ks * 8;
        uint32_t b00 = Bb[kb * BSTW];
        uint32_t b01 = Bb[kb * BSTW + 4 * BSTW];
        uint32_t b10 = Bb[kb * BSTW + 8];
        uint32_t b11 = Bb[kb * BSTW + 4 * BSTW + 8];
#pragma unroll
        for (int mt = 0; mt < 2; mt++) {
            const uint32_t* Am = Ab + mt * 16 * AST + kb;
            uint32_t a0 = Am[0];
            uint32_t a1 = Am[8 * AST];
            uint32_t a2 = Am[4];
            uint32_t a3 = Am[8 * AST + 4];
            mma_tf32(c[mt][0], a0, a1, a2, a3, b00, b01);
            mma_tf32(c[mt][1], a0, a1, a2, a3, b10, b11);
        }
    }
}

// ---------------------------------------------------------------------------
// K1: H[row,h] = leaky(emb[row,:] @ Qw + Qb)   (tf32 tensor cores)
// ---------------------------------------------------------------------------
__global__ void __launch_bounds__(NT) k1_qgemm(const float* __restrict__ emb,
                                               const float* __restrict__ Qw,
                                               const float* __restrict__ Qb) {
    extern __shared__ uint32_t sm[];
    uint32_t* As = sm;
    uint32_t* Bs = sm + AS_WORDS;
    const int t = threadIdx.x;
    const int lane = t & 31;
    const int warp = t >> 5;
    const int n0 = (warp & 7) * 16;
    const int m0 = (warp >> 3) * 32;
    const int row0 = blockIdx.x * RT;

    stage_A(As, emb + (size_t)row0 * CC, t);
    stage_B(Bs, Qw, t);
    __syncthreads();

    float c[2][2][4];
#pragma unroll
    for (int mt = 0; mt < 2; mt++)
#pragma unroll
        for (int nt = 0; nt < 2; nt++)
#pragma unroll
            for (int i = 0; i < 4; i++) c[mt][nt][i] = 0.f;

    gemm_tc_128(As, Bs, lane, m0, n0, c);

#pragma unroll
    for (int nt = 0; nt < 2; nt++) {
        const int col = n0 + nt * 8 + 2 * (lane & 3);
        const float2 bias = *(const float2*)(Qb + col);
#pragma unroll
        for (int mt = 0; mt < 2; mt++) {
            const int r0 = row0 + m0 + mt * 16 + (lane >> 2);
            float2 v0 = make_float2(leaky(c[mt][nt][0] + bias.x),
                                    leaky(c[mt][nt][1] + bias.y));
            float2 v1 = make_float2(leaky(c[mt][nt][2] + bias.x),
                                    leaky(c[mt][nt][3] + bias.y));
            *(float2*)&g_H[(size_t)r0 * HH + col] = v0;
            *(float2*)&g_H[(size_t)(r0 + 8) * HH + col] = v1;
        }
    }
}

// ---------------------------------------------------------------------------
// K2: wsh[b,n,h] = sum_k H[b,js[k],h]*ws[k] / (sum_k ws + eps)  (fp32)
// ---------------------------------------------------------------------------
__global__ void __launch_bounds__(128) k2_gather(const float* __restrict__ weights,
                                                 const int* __restrict__ ns) {
    const int n = blockIdx.x;
    const int t = threadIdx.x;
    const int c4 = t & 31;
    const int kg = t >> 5;

    __shared__ float ws[KK];
    __shared__ int   js[KK];
    __shared__ float wsum_s;
    __shared__ float4 red0[4][32];
    __shared__ float4 red1[4][32];

    if (t < KK) {
        int j = ns[n * KK + t];
        js[t] = j;
        float w = weights[(size_t)n * NN + j];
        ws[t] = w;
#pragma unroll
        for (int off = 16; off; off >>= 1)
            w += __shfl_xor_sync(0xffffffffu, w, off);
        if (t == 0) wsum_s = w;
    }
    __syncthreads();

    const float* H0 = g_H;
    const float* H1 = g_H + (size_t)NN * HH;
    float4 a0 = make_float4(0.f, 0.f, 0.f, 0.f);
    float4 a1 = make_float4(0.f, 0.f, 0.f, 0.f);
#pragma unroll
    for (int k = kg; k < KK; k += 4) {
        const int j = js[k];
        const float w = ws[k];
        const float4 h0 = *(const float4*)&H0[(size_t)j * HH + 4 * c4];
        const float4 h1 = *(const float4*)&H1[(size_t)j * HH + 4 * c4];
        a0.x = fmaf(h0.x, w, a0.x); a0.y = fmaf(h0.y, w, a0.y);
        a0.z = fmaf(h0.z, w, a0.z); a0.w = fmaf(h0.w, w, a0.w);
        a1.x = fmaf(h1.x, w, a1.x); a1.y = fmaf(h1.y, w, a1.y);
        a1.z = fmaf(h1.z, w, a1.z); a1.w = fmaf(h1.w, w, a1.w);
    }
    red0[kg][c4] = a0;
    red1[kg][c4] = a1;
    __syncthreads();

    if (t < 64) {
        const int b = t >> 5;
        const int c = t & 31;
        const float4 p0 = b ? red1[0][c] : red0[0][c];
        const float4 p1 = b ? red1[1][c] : red0[1][c];
        const float4 p2 = b ? red1[2][c] : red0[2][c];
        const float4 p3 = b ? red1[3][c] : red0[3][c];
        const float inv = 1.f / (wsum_s + EPS);
        float4 o;
        o.x = (p0.x + p1.x + p2.x + p3.x) * inv;
        o.y = (p0.y + p1.y + p2.y + p3.y) * inv;
        o.z = (p0.z + p1.z + p2.z + p3.z) * inv;
        o.w = (p0.w + p1.w + p2.w + p3.w) * inv;
        *(float4*)&g_wsh[((size_t)b * NN + n) * HH + 4 * c] = o;
    }
}

// ---------------------------------------------------------------------------
// K3: out = normalize(leaky([emb | wsh] @ Ww + Wb)), two tf32 K=128 stages
// ---------------------------------------------------------------------------
__global__ void __launch_bounds__(NT) k3_out(const float* __restrict__ emb,
                                             const float* __restrict__ Ww,
                                             const float* __restrict__ Wb,
                                             float* __restrict__ out) {
    extern __shared__ uint32_t sm[];
    uint32_t* As = sm;
    uint32_t* Bs = sm + AS_WORDS;
    const int t = threadIdx.x;
    const int lane = t & 31;
    const int warp = t >> 5;
    const int n0 = (warp & 7) * 16;
    const int m0 = (warp >> 3) * 32;
    const int row0 = blockIdx.x * RT;

    float c[2][2][4];
#pragma unroll
    for (int mt = 0; mt < 2; mt++)
#pragma unroll
        for (int nt = 0; nt < 2; nt++)
#pragma unroll
            for (int i = 0; i < 4; i++) c[mt][nt][i] = 0.f;

    // stage 0: A = emb rows, B = Ww[0:128,:]
    stage_A(As, emb + (size_t)row0 * CC, t);
    stage_B(Bs, Ww, t);
    __syncthreads();
    gemm_tc_128(As, Bs, lane, m0, n0, c);
    __syncthreads();

    // stage 1: A = wsh rows, B = Ww[128:256,:]
    stage_A(As, g_wsh + (size_t)row0 * HH, t);
    stage_B(Bs, Ww + 128 * HH, t);
    __syncthreads();
    gemm_tc_128(As, Bs, lane, m0, n0, c);
    __syncthreads();   // all warps done reading As before reuse as Vs

    // epilogue: bias + leaky into Vs, then row-norm and store
    float* Vs = (float*)As;   // 64 x AST
#pragma unroll
    for (int nt = 0; nt < 2; nt++) {
        const int col = n0 + nt * 8 + 2 * (lane & 3);
        const float2 bias = *(const float2*)(Wb + col);
#pragma unroll
        for (int mt = 0; mt < 2; mt++) {
            const int r = m0 + mt * 16 + (lane >> 2);
            *(float2*)&Vs[r * AST + col] =
                make_float2(leaky(c[mt][nt][0] + bias.x),
                            leaky(c[mt][nt][1] + bias.y));
            *(float2*)&Vs[(r + 8) * AST + col] =
                make_float2(leaky(c[mt][nt][2] + bias.x),
                            leaky(c[mt][nt][3] + bias.y));
        }
    }
    __syncthreads();

    // 8 threads per row, 16 cols each
    const int row = t >> 3;
    const int q = t & 7;
    float4 vv[4];
    float ssq = 0.f;
#pragma unroll
    for (int i = 0; i < 4; i++) {
        vv[i] = *(const float4*)&Vs[row * AST + q * 16 + i * 4];
        ssq = fmaf(vv[i].x, vv[i].x, ssq);
        ssq = fmaf(vv[i].y, vv[i].y, ssq);
        ssq = fmaf(vv[i].z, vv[i].z, ssq);
        ssq = fmaf(vv[i].w, vv[i].w, ssq);
    }
    ssq += __shfl_xor_sync(0xffffffffu, ssq, 1);
    ssq += __shfl_xor_sync(0xffffffffu, ssq, 2);
    ssq += __shfl_xor_sync(0xffffffffu, ssq, 4);
    const float inv = 1.f / (sqrtf(ssq) + EPS);
    float* o = out + (size_t)(row0 + row) * HH + q * 16;
#pragma unroll
    for (int i = 0; i < 4; i++) {
        *(float4*)(o + i * 4) = make_float4(vv[i].x * inv, vv[i].y * inv,
                                            vv[i].z * inv, vv[i].w * inv);
    }
}

// ---------------------------------------------------------------------------
extern "C" void kernel_launch(void* const* d_in, const int* in_sizes, int n_in,
                              void* d_out, int out_size) {
    const float* emb     = (const float*)d_in[0];  // (B, N, C)
    const float* weights = (const float*)d_in[1];  // (N, N)
    const int*   ns      = (const int*)  d_in[2];  // (N, K)
    const float* Qw      = (const float*)d_in[3];  // (C, H)
    const float* Qb      = (const float*)d_in[4];  // (H,)
    const float* Ww      = (const float*)d_in[5];  // (C+H, H)
    const float* Wb      = (const float*)d_in[6];  // (H,)
    float* out = (float*)d_out;                    // (B, N, H)

    (void)in_sizes; (void)n_in; (void)out_size;

    cudaFuncSetAttribute(k1_qgemm, cudaFuncAttributeMaxDynamicSharedMemorySize,
                         SMEM_BYTES);
    cudaFuncSetAttribute(k3_out, cudaFuncAttributeMaxDynamicSharedMemorySize,
                         SMEM_BYTES);

    k1_qgemm<<<(BB * NN) / RT, NT, SMEM_BYTES>>>(emb, Qw, Qb);
    k2_gather<<<NN, 128>>>(weights, ns);
    k3_out<<<(BB * NN) / RT, NT, SMEM_BYTES>>>(emb, Ww, Wb, out);
}

// round 12
// speedup vs baseline: 1.0862x; 1.0862x over previous
#include <cuda_runtime.h>
#include <cuda_fp16.h>
#include <math.h>
#include <stdint.h>

#define BB 2
#define NN 8192
#define KK 32
#define CC 128
#define HH 128
#define ALPHA 0.3f
#define EPS 1e-6f

#define RT 64                  // rows per block tile
#define AST 132                // As/Vs stride in 4B words (132%32==4 -> cf frags)
#define BSTW 132               // Bs stride in 4B words
#define AS_WORDS (RT * AST)    // 8448
#define BS_WORDS (128 * BSTW)  // 16896
#define SMEM_BYTES ((AS_WORDS + BS_WORDS) * 4)   // 101376 B -> 2 blocks/SM
#define NT 256                 // threads per GEMM block (measured best)

__device__ __half   g_H[(size_t)BB * NN * HH];     // fp16 hidden, 4 MB
__device__ float    g_wsh[(size_t)BB * NN * HH];   // weighted-sum hidden, 8 MB
__device__ uint32_t g_Qw32[CC * HH];               // tf32 pre-converted Qw
__device__ uint32_t g_Ww32[(CC + HH) * HH];        // tf32 pre-converted Ww

__device__ __forceinline__ uint32_t to_tf32(float f) {
    uint32_t r;
    asm("cvt.rna.tf32.f32 %0, %1;" : "=r"(r) : "f"(f));
    return r;
}
__device__ __forceinline__ void mma_tf32(float c[4], uint32_t a0, uint32_t a1,
                                         uint32_t a2, uint32_t a3,
                                         uint32_t b0, uint32_t b1) {
    asm("mma.sync.aligned.m16n8k8.row.col.f32.tf32.tf32.f32 "
        "{%0,%1,%2,%3}, {%4,%5,%6,%7}, {%8,%9}, {%0,%1,%2,%3};"
        : "+f"(c[0]), "+f"(c[1]), "+f"(c[2]), "+f"(c[3])
        : "r"(a0), "r"(a1), "r"(a2), "r"(a3), "r"(b0), "r"(b1));
}
__device__ __forceinline__ float leaky(float v) {
    return (v >= 0.f) ? v : ALPHA * v;
}

// ---------------------------------------------------------------------------
// K0: one-shot tf32 pre-conversion of the weight matrices
// ---------------------------------------------------------------------------
__global__ void k0_prep(const float* __restrict__ Qw,
                        const float* __restrict__ Ww) {
    const int i = blockIdx.x * blockDim.x + threadIdx.x;
    if (i < CC * HH) g_Qw32[i] = to_tf32(Qw[i]);
    if (i < (CC + HH) * HH) g_Ww32[i] = to_tf32(Ww[i]);
}

// ---- stage A: 64 rows x 128 cols fp32 -> tf32 bits, stride AST ------------
__device__ __forceinline__ void stage_A(uint32_t* __restrict__ As,
                                        const float* __restrict__ src, int t) {
    const float4* s4 = (const float4*)src;
#pragma unroll
    for (int i = 0; i < (RT * CC / 4) / NT; i++) {   // 8 iters
        int id = t + i * NT;
        int row = id >> 5;
        int c = (id & 31) << 2;
        float4 v = s4[id];
        uint4 u = make_uint4(to_tf32(v.x), to_tf32(v.y), to_tf32(v.z), to_tf32(v.w));
        *(uint4*)&As[row * AST + c] = u;
    }
}
// ---- stage B: pre-converted tf32 weights, raw uint4 copy ------------------
__device__ __forceinline__ void stage_B(uint32_t* __restrict__ Bs,
                                        const uint32_t* __restrict__ W32, int t) {
    const uint4* s4 = (const uint4*)W32;
#pragma unroll
    for (int i = 0; i < (128 * 128 / 4) / NT; i++) {  // 16 iters
        int id = t + i * NT;
        int row = id >> 5;
        int c = (id & 31) << 2;
        *(uint4*)&Bs[row * BSTW + c] = s4[id];
    }
}

// ---- tensor-core mainloop over K=128 --------------------------------------
// 8 warps: warp w owns cols n0=w*16 (2 n-tiles), all 64 rows (4 m-tiles).
__device__ __forceinline__ void gemm_tc_128(const uint32_t* __restrict__ As,
                                            const uint32_t* __restrict__ Bs,
                                            int lane, int n0,
                                            float c[4][2][4]) {
    const uint32_t* Ab = As + (lane >> 2) * AST + (lane & 3);
    const uint32_t* Bb = Bs + (lane & 3) * BSTW + n0 + (lane >> 2);
#pragma unroll 4
    for (int ks = 0; ks < 16; ks++) {
        const int kb = ks * 8;
        uint32_t b00 = Bb[kb * BSTW];
        uint32_t b01 = Bb[kb * BSTW + 4 * BSTW];
        uint32_t b10 = Bb[kb * BSTW + 8];
        uint32_t b11 = Bb[kb * BSTW + 4 * BSTW + 8];
#pragma unroll
        for (int mt = 0; mt < 4; mt++) {
            const uint32_t* Am = Ab + mt * 16 * AST + kb;
            uint32_t a0 = Am[0];
            uint32_t a1 = Am[8 * AST];
            uint32_t a2 = Am[4];
            uint32_t a3 = Am[8 * AST + 4];
            mma_tf32(c[mt][0], a0, a1, a2, a3, b00, b01);
            mma_tf32(c[mt][1], a0, a1, a2, a3, b10, b11);
        }
    }
}

// ---------------------------------------------------------------------------
// K1: H[row,h] = leaky(emb[row,:] @ Qw + Qb) -> fp16
// ---------------------------------------------------------------------------
__global__ void __launch_bounds__(NT) k1_qgemm(const float* __restrict__ emb,
                                               const float* __restrict__ Qb) {
    extern __shared__ uint32_t sm[];
    uint32_t* As = sm;
    uint32_t* Bs = sm + AS_WORDS;
    const int t = threadIdx.x;
    const int lane = t & 31;
    const int n0 = (t >> 5) * 16;
    const int row0 = blockIdx.x * RT;

    stage_A(As, emb + (size_t)row0 * CC, t);
    stage_B(Bs, g_Qw32, t);
    __syncthreads();

    float c[4][2][4];
#pragma unroll
    for (int mt = 0; mt < 4; mt++)
#pragma unroll
        for (int nt = 0; nt < 2; nt++)
#pragma unroll
            for (int i = 0; i < 4; i++) c[mt][nt][i] = 0.f;

    gemm_tc_128(As, Bs, lane, n0, c);

#pragma unroll
    for (int nt = 0; nt < 2; nt++) {
        const int col = n0 + nt * 8 + 2 * (lane & 3);
        const float2 bias = *(const float2*)(Qb + col);
#pragma unroll
        for (int mt = 0; mt < 4; mt++) {
            const int r0 = row0 + mt * 16 + (lane >> 2);
            __half2 v0 = __floats2half2_rn(leaky(c[mt][nt][0] + bias.x),
                                           leaky(c[mt][nt][1] + bias.y));
            __half2 v1 = __floats2half2_rn(leaky(c[mt][nt][2] + bias.x),
                                           leaky(c[mt][nt][3] + bias.y));
            *(__half2*)&g_H[(size_t)r0 * HH + col] = v0;
            *(__half2*)&g_H[(size_t)(r0 + 8) * HH + col] = v1;
        }
    }
}

// ---------------------------------------------------------------------------
// K2: wsh[b,n,h] = sum_k H[b,js[k],h]*ws[k] / (sum_k ws + eps)
// H is fp16 -> half the L2 gather traffic; math in fp32.
// ---------------------------------------------------------------------------
__global__ void __launch_bounds__(128) k2_gather(const float* __restrict__ weights,
                                                 const int* __restrict__ ns) {
    const int n = blockIdx.x;
    const int t = threadIdx.x;
    const int c4 = t & 31;   // column group: h = 4*c4 .. 4*c4+3
    const int kg = t >> 5;   // k-group 0..3

    __shared__ float ws[KK];
    __shared__ int   js[KK];
    __shared__ float wsum_s;
    __shared__ float4 red0[4][32];
    __shared__ float4 red1[4][32];

    if (t < KK) {
        int j = ns[n * KK + t];
        js[t] = j;
        float w = weights[(size_t)n * NN + j];
        ws[t] = w;
#pragma unroll
        for (int off = 16; off; off >>= 1)
            w += __shfl_xor_sync(0xffffffffu, w, off);
        if (t == 0) wsum_s = w;
    }
    __syncthreads();

    const __half* H0 = g_H;
    const __half* H1 = g_H + (size_t)NN * HH;
    float4 a0 = make_float4(0.f, 0.f, 0.f, 0.f);
    float4 a1 = make_float4(0.f, 0.f, 0.f, 0.f);
#pragma unroll
    for (int k = kg; k < KK; k += 4) {
        const int j = js[k];
        const float w = ws[k];
        const __half2* p0 = (const __half2*)(H0 + (size_t)j * HH + 4 * c4);
        const __half2* p1 = (const __half2*)(H1 + (size_t)j * HH + 4 * c4);
        float2 x0 = __half22float2(p0[0]);
        float2 y0 = __half22float2(p0[1]);
        float2 x1 = __half22float2(p1[0]);
        float2 y1 = __half22float2(p1[1]);
        a0.x = fmaf(x0.x, w, a0.x); a0.y = fmaf(x0.y, w, a0.y);
        a0.z = fmaf(y0.x, w, a0.z); a0.w = fmaf(y0.y, w, a0.w);
        a1.x = fmaf(x1.x, w, a1.x); a1.y = fmaf(x1.y, w, a1.y);
        a1.z = fmaf(y1.x, w, a1.z); a1.w = fmaf(y1.y, w, a1.w);
    }
    red0[kg][c4] = a0;
    red1[kg][c4] = a1;
    __syncthreads();

    if (t < 64) {
        const int b = t >> 5;
        const int c = t & 31;
        const float4 p0 = b ? red1[0][c] : red0[0][c];
        const float4 p1 = b ? red1[1][c] : red0[1][c];
        const float4 p2 = b ? red1[2][c] : red0[2][c];
        const float4 p3 = b ? red1[3][c] : red0[3][c];
        const float inv = 1.f / (wsum_s + EPS);
        float4 o;
        o.x = (p0.x + p1.x + p2.x + p3.x) * inv;
        o.y = (p0.y + p1.y + p2.y + p3.y) * inv;
        o.z = (p0.z + p1.z + p2.z + p3.z) * inv;
        o.w = (p0.w + p1.w + p2.w + p3.w) * inv;
        *(float4*)&g_wsh[((size_t)b * NN + n) * HH + 4 * c] = o;
    }
}

// ---------------------------------------------------------------------------
// K3: out = normalize(leaky([emb | wsh] @ Ww + Wb)), two tf32 K=128 stages
// ---------------------------------------------------------------------------
__global__ void __launch_bounds__(NT) k3_out(const float* __restrict__ emb,
                                             const float* __restrict__ Wb,
                                             float* __restrict__ out) {
    extern __shared__ uint32_t sm[];
    uint32_t* As = sm;
    uint32_t* Bs = sm + AS_WORDS;
    const int t = threadIdx.x;
    const int lane = t & 31;
    const int n0 = (t >> 5) * 16;
    const int row0 = blockIdx.x * RT;

    float c[4][2][4];
#pragma unroll
    for (int mt = 0; mt < 4; mt++)
#pragma unroll
        for (int nt = 0; nt < 2; nt++)
#pragma unroll
            for (int i = 0; i < 4; i++) c[mt][nt][i] = 0.f;

    // stage 0: A = emb rows, B = Ww[0:128,:]
    stage_A(As, emb + (size_t)row0 * CC, t);
    stage_B(Bs, g_Ww32, t);
    __syncthreads();
    gemm_tc_128(As, Bs, lane, n0, c);
    __syncthreads();

    // stage 1: A = wsh rows, B = Ww[128:256,:]
    stage_A(As, g_wsh + (size_t)row0 * HH, t);
    stage_B(Bs, g_Ww32 + 128 * HH, t);
    __syncthreads();
    gemm_tc_128(As, Bs, lane, n0, c);
    __syncthreads();   // all warps done reading As before reuse as Vs

    // epilogue: bias + leaky into Vs, then row-norm and store
    float* Vs = (float*)As;   // 64 x AST
#pragma unroll
    for (int nt = 0; nt < 2; nt++) {
        const int col = n0 + nt * 8 + 2 * (lane & 3);
        const float2 bias = *(const float2*)(Wb + col);
#pragma unroll
        for (int mt = 0; mt < 4; mt++) {
            const int r = mt * 16 + (lane >> 2);
            *(float2*)&Vs[r * AST + col] =
                make_float2(leaky(c[mt][nt][0] + bias.x),
                            leaky(c[mt][nt][1] + bias.y));
            *(float2*)&Vs[(r + 8) * AST + col] =
                make_float2(leaky(c[mt][nt][2] + bias.x),
                            leaky(c[mt][nt][3] + bias.y));
        }
    }
    __syncthreads();

    // 4 threads per row, 32 cols each
    const int row = t >> 2;
    const int q = t & 3;
    float4 vv[8];
    float ssq = 0.f;
#pragma unroll
    for (int i = 0; i < 8; i++) {
        vv[i] = *(const float4*)&Vs[row * AST + q * 32 + i * 4];
        ssq = fmaf(vv[i].x, vv[i].x, ssq);
        ssq = fmaf(vv[i].y, vv[i].y, ssq);
        ssq = fmaf(vv[i].z, vv[i].z, ssq);
        ssq = fmaf(vv[i].w, vv[i].w, ssq);
    }
    ssq += __shfl_xor_sync(0xffffffffu, ssq, 1);
    ssq += __shfl_xor_sync(0xffffffffu, ssq, 2);
    const float inv = 1.f / (sqrtf(ssq) + EPS);
    float* o = out + (size_t)(row0 + row) * HH + q * 32;
#pragma unroll
    for (int i = 0; i < 8; i++) {
        *(float4*)(o + i * 4) = make_float4(vv[i].x * inv, vv[i].y * inv,
                                            vv[i].z * inv, vv[i].w * inv);
    }
}

// ---------------------------------------------------------------------------
extern "C" void kernel_launch(void* const* d_in, const int* in_sizes, int n_in,
                              void* d_out, int out_size) {
    const float* emb     = (const float*)d_in[0];  // (B, N, C)
    const float* weights = (const float*)d_in[1];  // (N, N)
    const int*   ns      = (const int*)  d_in[2];  // (N, K)
    const float* Qw      = (const float*)d_in[3];  // (C, H)
    const float* Qb      = (const float*)d_in[4];  // (H,)
    const float* Ww      = (const float*)d_in[5];  // (C+H, H)
    const float* Wb      = (const float*)d_in[6];  // (H,)
    float* out = (float*)d_out;                    // (B, N, H)

    (void)in_sizes; (void)n_in; (void)out_size;

    cudaFuncSetAttribute(k1_qgemm, cudaFuncAttributeMaxDynamicSharedMemorySize,
                         SMEM_BYTES);
    cudaFuncSetAttribute(k3_out, cudaFuncAttributeMaxDynamicSharedMemorySize,
                         SMEM_BYTES);

    k0_prep<<<((CC + HH) * HH + 255) / 256, 256>>>(Qw, Ww);
    k1_qgemm<<<(BB * NN) / RT, NT, SMEM_BYTES>>>(emb, Qb);
    k2_gather<<<NN, 128>>>(weights, ns);
    k3_out<<<(BB * NN) / RT, NT, SMEM_BYTES>>>(emb, Wb, out);
}